// round 5
// baseline (speedup 1.0000x reference)
#include <cuda_runtime.h>
#include <cstdint>
#include <math.h>

#define LEVELS 3
#define BINS 9
#define NATOMS 51
#define ADIM 6
#define NB 4096
#define ROWS 162                          // LEVELS*ADIM*BINS
#define SLAB 8262                         // ROWS*NATOMS floats
#define SLAB_BYTES 33048                  // SLAB*4 (== 8 mod 16)
#define LOAD_BYTES 33056                  // rounded-up bulk-load size
#define V_MIN_C (-10.0f)
#define V_MAX_C (10.0f)
#define DZ_C (0.4f)

#define THREADS 256

// dyn smem layout (bytes):
//   [0,16)            mbarrier (8 B used, padded for alignment)
//   [16, 16+33056)    load buffer (16B aligned); slab data starts at +m
//   [33072, +33064)   result buffer; result starts at +m (matches global mod 16)
#define OFF_MBAR 0
#define OFF_LOAD 16
#define OFF_RES  33072
#define DYN_BYTES 66144

__global__ __launch_bounds__(THREADS)
void c2f_kernel(const float* __restrict__ q,
                const float* __restrict__ reward,
                const float* __restrict__ discount,
                const float* __restrict__ act,
                const float* __restrict__ support,
                const float* __restrict__ low0,
                const float* __restrict__ high0,
                float* __restrict__ out)
{
    const int b = blockIdx.x;
    const int t = threadIdx.x;
    const int m = (b & 1) ? 8 : 0;        // slab global misalignment mod 16 (bytes)

    extern __shared__ __align__(16) char dyn[];
    const uint32_t smem_base = (uint32_t)__cvta_generic_to_shared(dyn);
    const uint32_t mbar = smem_base + OFF_MBAR;

    float* sp = reinterpret_cast<float*>(dyn + OFF_LOAD + m);  // staged probs
    float* so = reinterpret_cast<float*>(dyn + OFF_RES + m);   // staged result

    __shared__ float swl[NATOMS];
    __shared__ float swu[NATOMS];
    __shared__ int   slower[NATOMS];

    // ---- mbarrier init (before any wait) ----
    if (t == 0) {
        asm volatile("mbarrier.init.shared.b64 [%0], 1;" :: "r"(mbar) : "memory");
    }

    // ---- Phase 1a: per-atom projection coefficients (block-uniform tables) ----
    if (t < NATOMS) {
        const float r = reward[b];
        const float d = discount[b];
        const float z = support[t];
        float Tz = fminf(fmaxf(r + d * z, V_MIN_C), V_MAX_C);
        float bc = (Tz - V_MIN_C) / DZ_C;
        int lo = (int)floorf(bc);
        int up = (int)ceilf(bc);
        if (up > 0 && lo == up) lo -= 1;              // reference fixup 1
        if (lo < NATOMS - 1 && lo == up) up += 1;     // reference fixup 2 => up==lo+1
        slower[t] = lo;                               // in [0,49]
        swl[t] = (float)up - bc;
        swu[t] = bc - (float)lo;
    }

    // ---- Phase 1b: encode + decode (6 dims) ----
    if (t >= 64 && t < 64 + ADIM) {
        const int dim = t - 64;
        const float a = act[b * ADIM + dim];
        float low = low0[dim], high = high0[dim];
        float idx[LEVELS];
        #pragma unroll
        for (int lvl = 0; lvl < LEVELS; lvl++) {
            float sr = (high - low) / (float)BINS;
            float id = floorf((a - low) / sr);
            id = fminf(fmaxf(id, 0.0f), (float)(BINS - 1));
            float na = fminf(fmaxf(low + sr * id, -1.0f), 1.0f);
            low  = fmaxf(-1.0f, na);
            high = fminf(1.0f, na + sr);
            idx[lvl] = id;
        }
        low = low0[dim]; high = high0[dim];
        #pragma unroll
        for (int lvl = 0; lvl < LEVELS; lvl++) {
            float sr = (high - low) / (float)BINS;
            float cont = low + sr * idx[lvl];
            low  = fmaxf(-1.0f, cont);
            high = fminf(1.0f, cont + sr);
        }
        out[(size_t)NB * SLAB + (size_t)b * ADIM + dim] = 0.5f * (high + low);
    }

    __syncthreads();   // mbar init + tables visible

    // ---- TMA bulk load: aligned-down source, fixed 33056 B ----
    if (t == 0) {
        const char* src = reinterpret_cast<const char*>(q) + (size_t)b * SLAB_BYTES - m;
        asm volatile("mbarrier.arrive.expect_tx.shared.b64 _, [%0], %1;"
                     :: "r"(mbar), "r"((uint32_t)LOAD_BYTES) : "memory");
        asm volatile("cp.async.bulk.shared::cta.global.mbarrier::complete_tx::bytes "
                     "[%0], [%1], %2, [%3];"
                     :: "r"(smem_base + OFF_LOAD), "l"(src),
                        "r"((uint32_t)LOAD_BYTES), "r"(mbar) : "memory");
    }

    // ---- all threads wait for the slab ----
    {
        asm volatile(
            "{\n\t"
            ".reg .pred P;\n\t"
            "WAIT_%=:\n\t"
            "mbarrier.try_wait.parity.acquire.cta.shared::cta.b64 P, [%0], 0, 0x989680;\n\t"
            "@!P bra WAIT_%=;\n\t"
            "}"
            :: "r"(mbar) : "memory");
    }

    // ---- Phase 2: one thread per row, single walk j=0..50 with gap zero-fill.
    //      lower[] block-uniform & nondecreasing -> uniform branches.
    if (t < ROWS) {
        const float* pr = sp + t * NATOMS;   // stride 51 (odd) -> conflict-free
        float* po = so + t * NATOMS;
        int kcur = slower[0];
        for (int k = 0; k < kcur; k++) po[k] = 0.0f;          // prefix zeros
        float accA = 0.0f, accB = 0.0f, carryB = 0.0f;
        #pragma unroll 1
        for (int j = 0; j < NATOMS; j++) {
            const int kj = slower[j];        // uniform broadcast
            if (kj != kcur) {                // uniform branch
                po[kcur] = accA + carryB;
                if (kj == kcur + 1) {
                    carryB = accB;
                } else {
                    po[kcur + 1] = accB;
                    for (int k = kcur + 2; k < kj; k++) po[k] = 0.0f;  // gap zeros
                    carryB = 0.0f;
                }
                accA = 0.0f; accB = 0.0f; kcur = kj;
            }
            const float p = pr[j];
            accA = fmaf(p, swl[j], accA);
            accB = fmaf(p, swu[j], accB);
        }
        po[kcur] = accA + carryB;
        po[kcur + 1] = accB;                                   // kcur<=49 -> safe
        for (int k = kcur + 2; k < NATOMS; k++) po[k] = 0.0f;  // suffix zeros
    }
    __syncthreads();

    // ---- Phase 3: bulk store of aligned interior + 2 scalar floats ----
    if (t == 0) {
        float* dst = out + (size_t)b * SLAB;
        if (m == 8) { dst[0] = so[0]; dst[1] = so[1]; }                // head
        else        { dst[SLAB - 2] = so[SLAB - 2]; dst[SLAB - 1] = so[SLAB - 1]; } // tail
        asm volatile("fence.proxy.async.shared::cta;" ::: "memory");
        // aligned interior: 33040 bytes. For m==8 skip first 8 B; for m==0 skip last 8 B.
        const uint32_t src_s = smem_base + OFF_RES + ((m == 8) ? 16u : 0u);
        char* dst_al = reinterpret_cast<char*>(out) + (size_t)b * SLAB_BYTES + ((m == 8) ? 8 : 0);
        asm volatile("cp.async.bulk.global.shared::cta.bulk_group [%0], [%1], %2;"
                     :: "l"(dst_al), "r"(src_s), "r"((uint32_t)33040) : "memory");
        asm volatile("cp.async.bulk.commit_group;" ::: "memory");
        asm volatile("cp.async.bulk.wait_group 0;" ::: "memory");
    }
}

extern "C" void kernel_launch(void* const* d_in, const int* in_sizes, int n_in,
                              void* d_out, int out_size)
{
    const float* q        = (const float*)d_in[0];
    const float* reward   = (const float*)d_in[1];
    const float* discount = (const float*)d_in[2];
    const float* act      = (const float*)d_in[3];
    const float* support  = (const float*)d_in[4];
    const float* low0     = (const float*)d_in[5];
    const float* high0    = (const float*)d_in[6];
    float* out = (float*)d_out;

    cudaFuncSetAttribute(c2f_kernel, cudaFuncAttributeMaxDynamicSharedMemorySize,
                         DYN_BYTES);
    c2f_kernel<<<NB, THREADS, DYN_BYTES>>>(q, reward, discount, act, support,
                                           low0, high0, out);
}